// round 10
// baseline (speedup 1.0000x reference)
#include <cuda_runtime.h>
#include <math.h>

#define Bn 16
#define Nn 1000
#define En 16000
#define NT 16000
#define EBASE 256000
#define ETOT 272000
#define TWOE 32000
#define HALFB 8
#define NLOW 8000         /* dsts 0..7999 have only their self loop (structural) */

#define H1n 8
#define F1 1024
#define EMBn 64
#define HIDn 128
#define BCAP 96

#define NCHUNK 400
#define CK 160

#define NBLK1 592         /* K1/K3: 4 CTAs/SM on 148 SMs (fits 152 too) */
#define NBLK2 296         /* K2: 2 CTAs/SM */
#define NTHR 256
#define NTOT1 (NBLK1 * NTHR)

// ------------------------- scratch -------------------------
__device__ __align__(16) float4 g_xf[NT];
__device__ float g_psrc[24];
__device__ float g_pdst[24];
__device__ int   g_cursor[NT];                 // zero at load; re-zeroed in K3 mlp1 phase
__device__ int   g_bucket[NT * BCAP];
__device__ __align__(16) float g_s[NT * 24];
__device__ __align__(16) float g_h2[NT * EMBn];
__device__ float g_a2s[NT];
__device__ float g_a2d[NT];
__device__ __align__(16) float g_x2t[64000 * 16];
__device__ float g_part[NCHUNK * 16 * HIDn];
__device__ float g_y1[16 * HIDn];
__device__ unsigned g_bc1, g_bg1;              // K1 barrier
__device__ unsigned g_bc3, g_bg3;              // K3 barrier

// ------------------------- helpers -------------------------
__device__ __forceinline__ void edge_sd(int e, const int* __restrict__ EI, int& src, int& dst) {
    if (e < EBASE) {
        int b   = e / TWOE;
        int rem = e - b * TWOE;
        src = EI[b * TWOE + rem] + b * Nn;
        int b2 = b + HALFB;
        dst = EI[b2 * TWOE + rem] + b2 * Nn;
    } else {
        src = dst = e - EBASE;
    }
}

__device__ __forceinline__ float warp_sum(float v) {
    #pragma unroll
    for (int o = 16; o > 0; o >>= 1) v += __shfl_xor_sync(0xffffffffu, v, o);
    return v;
}
__device__ __forceinline__ float leaky(float v) { return v > 0.f ? v : 0.2f * v; }
__device__ __forceinline__ float elu(float v)   { return v > 0.f ? v : (__expf(v) - 1.0f); }

__device__ __forceinline__ float2 ffma2(float2 a, float2 b, float2 c) {
    unsigned long long A = *reinterpret_cast<unsigned long long*>(&a);
    unsigned long long B = *reinterpret_cast<unsigned long long*>(&b);
    unsigned long long C = *reinterpret_cast<unsigned long long*>(&c);
    unsigned long long D;
    asm("fma.rn.f32x2 %0, %1, %2, %3;" : "=l"(D) : "l"(A), "l"(B), "l"(C));
    return *reinterpret_cast<float2*>(&D);
}

__device__ __forceinline__ void gbarN(unsigned* cnt, unsigned* gen, int nblk) {
    __threadfence();
    __syncthreads();
    if (threadIdx.x == 0) {
        unsigned g = *(volatile unsigned*)gen;
        if (atomicAdd(cnt, 1u) == (unsigned)(nblk - 1)) {
            *cnt = 0;
            __threadfence();
            atomicExch(gen, g + 1);
        } else {
            while (*(volatile unsigned*)gen == g) { __nanosleep(32); }
        }
    }
    __syncthreads();
    __threadfence();
}

// ================= K1: graph build + conv1 (high occupancy) =================
__global__ __launch_bounds__(NTHR, 4) void k1_kernel(
    const float* __restrict__ actions, const float* __restrict__ nodef,
    const int* __restrict__ EI,
    const float* __restrict__ W1, const float* __restrict__ as1,
    const float* __restrict__ ad1)
{
    int tid = threadIdx.x;
    int gidx = blockIdx.x * NTHR + tid;

    // --- phase A: node features + projections + bucket scatter ---
    if (gidx < NT) {
        float ax = actions[gidx * 2 + 0];
        float ay = actions[gidx * 2 + 1];
        float nf = nodef[gidx];
        g_xf[gidx] = make_float4(ax, ay, nf, 0.f);
    } else if (gidx < NT + 48) {
        int t = gidx - NT;
        int which = t / 24;
        int r = t % 24;
        int k = r / 8, h = r % 8;
        const float* att = which ? ad1 : as1;
        float s = 0.f;
        for (int c = 0; c < 128; c++)
            s += W1[k * F1 + h * 128 + c] * att[h * 128 + c];
        (which ? g_pdst : g_psrc)[k * 8 + h] = s;
    }
    #pragma unroll
    for (int q = 0; q < 2; q++) {
        int e = gidx * 2 + q;
        if (e < ETOT) {
            int src, dst;
            edge_sd(e, EI, src, dst);
            if (dst >= NLOW) {
                int pos = atomicAdd(&g_cursor[dst], 1);
                g_bucket[dst * BCAP + pos] = src;
            }
        }
    }
    gbarN(&g_bc1, &g_bg1, NBLK1);

    // --- phase B: conv1 attention ---
    if (gidx < 8000) {
        int d = gidx;
        float4 x = g_xf[d];
        float4 v0 = make_float4(x.x, x.y, x.z, x.x);
        float4 v1 = make_float4(x.y, x.z, x.x, x.y);
        float4 v2 = make_float4(x.z, x.x, x.y, x.z);
        float4* sp = (float4*)(g_s + d * 24);
        sp[0] = v0; sp[1] = v1; sp[2] = v2;
        sp[3] = v0; sp[4] = v1; sp[5] = v2;
    } else if (gidx < 8000 + 64000) {
        int i2 = gidx - 8000;
        int d = NLOW + (i2 >> 3), h = i2 & 7;
        float4 xd = g_xf[d];
        float p0 = g_psrc[h], p1 = g_psrc[8 + h], p2 = g_psrc[16 + h];
        float q0 = g_pdst[h], q1 = g_pdst[8 + h], q2 = g_pdst[16 + h];
        float adv = fmaf(xd.x, q0, fmaf(xd.y, q1, xd.z * q2));
        int deg = g_cursor[d];
        const int* bkt = g_bucket + d * BCAP;
        float se = 0.f, sx = 0.f, sy = 0.f, sz = 0.f;
        for (int e = 0; e < deg; e++) {
            int s = bkt[e];
            float4 x = g_xf[s];
            float a = fmaf(x.x, p0, fmaf(x.y, p1, x.z * p2)) + adv;
            float ea = __expf(leaky(a));
            se += ea;
            sx = fmaf(ea, x.x, sx);
            sy = fmaf(ea, x.y, sy);
            sz = fmaf(ea, x.z, sz);
        }
        float inv = 1.0f / se;
        float* sp = g_s + d * 24 + h * 3;
        sp[0] = sx * inv; sp[1] = sy * inv; sp[2] = sz * inv;
    }
}

// ================= K2: broadcast-GEMM  h2 = elu(s@W1+b1) @ W2  + attn2 =================
struct P3S {
    float4 w1t[F1];                // 16,384
    float  w2c[128][EMBn];         // 32,768 (reused as reduce scratch)
    float  sS[56 * 24];            //  5,376
    float  satt[128];              //    512
};

__global__ __launch_bounds__(NTHR, 2) void k2_kernel(
    const float* __restrict__ W1, const float* __restrict__ b1,
    const float* __restrict__ W2, const float* __restrict__ as2,
    const float* __restrict__ ad2)
{
    __shared__ __align__(16) P3S ps;
    int tid = threadIdx.x;
    int bid = blockIdx.x;

    int nrows = 54 + (bid < 16);                  // 296*54 + 16 = 16000
    int base = bid * 54 + min(bid, 16);
    int half = tid >> 7;                          // warp-uniform column half
    int slot = tid & 127;
    int row = base + slot;
    bool active = slot < nrows;

    for (int k = tid; k < F1; k += NTHR)
        ps.w1t[k] = make_float4(W1[k], W1[F1 + k], W1[2 * F1 + k], b1[k]);
    for (int i = tid; i < nrows * 24; i += NTHR)
        ps.sS[i] = g_s[base * 24 + i];
    if (tid < 128) ps.satt[tid] = (tid < 64) ? as2[tid] : ad2[tid - 64];

    float2 acc[16];
    #pragma unroll
    for (int j = 0; j < 16; j++) acc[j] = make_float2(0.f, 0.f);

    for (int ch = 0; ch < 8; ch++) {
        __syncthreads();
        {
            const float4* w2g = (const float4*)(W2 + ch * 128 * EMBn);
            float4* w2s = (float4*)ps.w2c;
            #pragma unroll
            for (int i = 0; i < 8; i++)
                w2s[tid + i * NTHR] = w2g[tid + i * NTHR];
        }
        __syncthreads();
        float s0 = 0.f, s1 = 0.f, s2 = 0.f;
        if (active) {
            s0 = ps.sS[slot * 24 + ch * 3 + 0];
            s1 = ps.sS[slot * 24 + ch * 3 + 1];
            s2 = ps.sS[slot * 24 + ch * 3 + 2];
        }
        for (int k = 0; k < 128; k++) {
            float4 w = ps.w1t[ch * 128 + k];                          // broadcast
            float x1 = fmaf(s0, w.x, fmaf(s1, w.y, fmaf(s2, w.z, w.w)));
            x1 = elu(x1);
            float2 xx = make_float2(x1, x1);
            const float4* brow = (const float4*)&ps.w2c[k][half * 32]; // broadcast
            #pragma unroll
            for (int j = 0; j < 8; j++) {
                float4 b = brow[j];
                acc[j * 2]     = ffma2(xx, make_float2(b.x, b.y), acc[j * 2]);
                acc[j * 2 + 1] = ffma2(xx, make_float2(b.z, b.w), acc[j * 2 + 1]);
            }
        }
    }
    if (active) {
        float4* dst = (float4*)(g_h2 + row * 64 + half * 32);
        const float4* a4 = (const float4*)acc;
        #pragma unroll
        for (int j = 0; j < 8; j++) dst[j] = a4[j];
    }
    float ss = 0.f, sd = 0.f;
    {
        const float* av = (const float*)acc;
        #pragma unroll
        for (int j = 0; j < 32; j++) {
            float v = av[j];
            ss = fmaf(v, ps.satt[half * 32 + j], ss);
            sd = fmaf(v, ps.satt[64 + half * 32 + j], sd);
        }
    }
    __syncthreads();
    float* red = ps.w2c[0];
    red[tid] = ss; red[256 + tid] = sd;
    __syncthreads();
    if (half == 0 && active) {
        g_a2s[row] = red[tid] + red[tid + 128];
        g_a2d[row] = red[256 + tid] + red[256 + tid + 128];
    }
}

// ================= K3: conv2 + mlp1 + reduce + mlp2 + out (high occupancy) =================
struct K3S {
    union {
        struct { float wbuf[8][BCAP]; int ibuf[8][BCAP]; } c2;   // 6,144
        float sx[2][CK * 16];                                    // 20,480
        struct { float y1s[16 * HIDn]; float y2s[16 * HIDn]; } t; // 16,384
    } u;
};

__global__ __launch_bounds__(NTHR, 4) void k3_kernel(
    const float* __restrict__ b2,
    const float* __restrict__ mw1, const float* __restrict__ mb1,
    const float* __restrict__ mw2, const float* __restrict__ mb2,
    const float* __restrict__ ow,  const float* __restrict__ ob,
    float* __restrict__ out)
{
    __shared__ __align__(16) K3S s;
    int tid = threadIdx.x;
    int bid = blockIdx.x;
    int gidx = bid * NTHR + tid;

    // --- phase A: conv2 softmax-agg ---
    {
        int lane = tid & 31;
        int w = (tid >> 5) & 7;
        int wg = gidx >> 5;
        for (int d = NLOW + wg; d < NT; d += NBLK1 * 8) {
            int deg = g_cursor[d];
            const int* bkt = g_bucket + d * BCAP;
            float adv = g_a2d[d];
            float se = 0.f;
            for (int e = lane; e < deg; e += 32) {
                int src = bkt[e];
                float ea = __expf(leaky(g_a2s[src] + adv));
                s.u.c2.wbuf[w][e] = ea;
                s.u.c2.ibuf[w][e] = src;
                se += ea;
            }
            __syncwarp();
            float2 acc = make_float2(0.f, 0.f);
            #pragma unroll 4
            for (int e = 0; e < deg; e++) {
                float ea = s.u.c2.wbuf[w][e];
                int src = s.u.c2.ibuf[w][e];
                float2 v = ((const float2*)(g_h2 + src * 64))[lane];
                acc.x = fmaf(ea, v.x, acc.x);
                acc.y = fmaf(ea, v.y, acc.y);
            }
            __syncwarp();
            se = warp_sum(se);
            float inv = 1.0f / se;
            float2 bb = ((const float2*)b2)[lane];
            int b = d / Nn, n = d - b * Nn;
            int c = lane * 2;
            g_x2t[(n * 64 + c) * 16 + b]     = elu(acc.x * inv + bb.x);
            g_x2t[(n * 64 + c + 1) * 16 + b] = elu(acc.y * inv + bb.y);
        }
        for (int i = gidx; i < NLOW * 32; i += NTOT1) {
            int d = i >> 5, ln = i & 31;
            float2 v = ((const float2*)(g_h2 + d * 64))[ln];
            float2 bb = ((const float2*)b2)[ln];
            int b = d / Nn, n = d - b * Nn;
            int c = ln * 2;
            g_x2t[(n * 64 + c) * 16 + b]     = elu(v.x + bb.x);
            g_x2t[(n * 64 + c + 1) * 16 + b] = elu(v.y + bb.y);
        }
    }
    gbarN(&g_bc3, &g_bg3, NBLK1);

    // --- phase B: mlp1 split-K stage 1 (+ cursor reset) ---
    {
        if (gidx < NT) g_cursor[gidx] = 0;
        int half = tid >> 7;
        int j = tid & 127;
        int g = bid * 2 + half;
        float4* sx4 = (float4*)s.u.sx[half];
        if (g < NCHUNK) {
            int k0 = g * CK;
            const float4* gx4 = (const float4*)(g_x2t + k0 * 16);
            #pragma unroll
            for (int i = 0; i < 5; i++)
                sx4[j + i * 128] = gx4[j + i * 128];
        }
        __syncthreads();
        if (g < NCHUNK) {
            int k0 = g * CK;
            float2 acc[8];
            #pragma unroll
            for (int p = 0; p < 8; p++) acc[p] = make_float2(0.f, 0.f);
            #pragma unroll 2
            for (int k = 0; k < CK; k++) {
                float wv = mw1[(k0 + k) * HIDn + j];
                float2 w2v = make_float2(wv, wv);
                float4 x0 = sx4[k * 4 + 0];
                float4 x1 = sx4[k * 4 + 1];
                float4 x2 = sx4[k * 4 + 2];
                float4 x3 = sx4[k * 4 + 3];
                acc[0] = ffma2(make_float2(x0.x, x0.y), w2v, acc[0]);
                acc[1] = ffma2(make_float2(x0.z, x0.w), w2v, acc[1]);
                acc[2] = ffma2(make_float2(x1.x, x1.y), w2v, acc[2]);
                acc[3] = ffma2(make_float2(x1.z, x1.w), w2v, acc[3]);
                acc[4] = ffma2(make_float2(x2.x, x2.y), w2v, acc[4]);
                acc[5] = ffma2(make_float2(x2.z, x2.w), w2v, acc[5]);
                acc[6] = ffma2(make_float2(x3.x, x3.y), w2v, acc[6]);
                acc[7] = ffma2(make_float2(x3.z, x3.w), w2v, acc[7]);
            }
            #pragma unroll
            for (int p = 0; p < 8; p++) {
                g_part[(g * 16 + 2 * p) * HIDn + j]     = acc[p].x;
                g_part[(g * 16 + 2 * p + 1) * HIDn + j] = acc[p].y;
            }
        }
    }
    gbarN(&g_bc3, &g_bg3, NBLK1);

    // --- phase C: mlp1 reduce ---
    if (gidx < 16 * HIDn) {
        int b = gidx >> 7, j = gidx & 127;
        float sum = 0.f;
        #pragma unroll 4
        for (int c = 0; c < NCHUNK; c++)
            sum += g_part[(c * 16 + b) * HIDn + j];
        sum += mb1[j];
        g_y1[b * HIDn + j] = fmaxf(sum, 0.f);
    }
    gbarN(&g_bc3, &g_bg3, NBLK1);

    // --- phase D: mlp2 (redundant per block) + output head ---
    if (bid < 8) {
        for (int i = tid; i < 16 * HIDn; i += NTHR) s.u.t.y1s[i] = g_y1[i];
        __syncthreads();
        if (tid < 128) {
            int j = tid;
            float acc[16];
            #pragma unroll
            for (int b = 0; b < 16; b++) acc[b] = 0.f;
            #pragma unroll 4
            for (int k = 0; k < HIDn; k++) {
                float wv = mw2[k * HIDn + j];
                #pragma unroll
                for (int b = 0; b < 16; b++)
                    acc[b] = fmaf(s.u.t.y1s[b * HIDn + k], wv, acc[b]);
            }
            #pragma unroll
            for (int b = 0; b < 16; b++)
                s.u.t.y2s[b * HIDn + j] = fmaxf(acc[b] + mb2[j], 0.f);
        }
        __syncthreads();
        int j = bid * 128 + (tid & 127);
        int bh = tid >> 7;
        if (j < Nn) {
            float acc[8];
            #pragma unroll
            for (int b = 0; b < 8; b++) acc[b] = 0.f;
            const float* y = s.u.t.y2s + bh * 8 * HIDn;
            #pragma unroll 4
            for (int k = 0; k < HIDn; k++) {
                float wv = ow[k * Nn + j];
                #pragma unroll
                for (int b = 0; b < 8; b++)
                    acc[b] = fmaf(y[b * HIDn + k], wv, acc[b]);
            }
            float obj = ob[j];
            #pragma unroll
            for (int b = 0; b < 8; b++) {
                float v = acc[b] + obj;
                out[(bh * 8 + b) * Nn + j] = 1.0f / (1.0f + __expf(-v));
            }
        }
    }
}

// ------------------------- launch -------------------------
extern "C" void kernel_launch(void* const* d_in, const int* in_sizes, int n_in,
                              void* d_out, int out_size) {
    const float* actions = (const float*)d_in[0];
    const float* nodef   = (const float*)d_in[1];
    const int*   ei      = (const int*)d_in[2];
    const float* W1  = (const float*)d_in[3];
    const float* as1 = (const float*)d_in[4];
    const float* ad1 = (const float*)d_in[5];
    const float* b1  = (const float*)d_in[6];
    const float* W2  = (const float*)d_in[7];
    const float* as2 = (const float*)d_in[8];
    const float* ad2 = (const float*)d_in[9];
    const float* b2  = (const float*)d_in[10];
    const float* mw1 = (const float*)d_in[11];
    const float* mb1 = (const float*)d_in[12];
    const float* mw2 = (const float*)d_in[13];
    const float* mb2 = (const float*)d_in[14];
    const float* ow  = (const float*)d_in[15];
    const float* ob  = (const float*)d_in[16];
    float* out = (float*)d_out;

    k1_kernel<<<NBLK1, NTHR>>>(actions, nodef, ei, W1, as1, ad1);
    k2_kernel<<<NBLK2, NTHR>>>(W1, b1, W2, as2, ad2);
    k3_kernel<<<NBLK1, NTHR>>>(b2, mw1, mb1, mw2, mb2, ow, ob, out);
}

// round 11
// speedup vs baseline: 1.0900x; 1.0900x over previous
#include <cuda_runtime.h>
#include <math.h>

#define Bn 16
#define Nn 1000
#define En 16000
#define NT 16000
#define EBASE 256000
#define ETOT 272000
#define TWOE 32000
#define HALFB 8
#define NLOW 8000         /* dsts 0..7999 have only their self loop (structural) */

#define H1n 8
#define F1 1024
#define EMBn 64
#define HIDn 128
#define BCAP 96

#define NCHUNK 400
#define CK 160

// ------------------------- scratch -------------------------
__device__ __align__(16) float4 g_xf[NT];
__device__ float g_psrc[24];
__device__ float g_pdst[24];
__device__ int   g_cursor[NT];                 // zero at load; re-zeroed in mlp1
__device__ int   g_bucket[NT * BCAP];
__device__ __align__(16) float g_s[NT * 24];
__device__ __align__(16) float g_h2[NT * EMBn];
__device__ float g_a2s[NT];
__device__ float g_a2d[NT];
__device__ __align__(16) float g_x2t[64000 * 16];
__device__ float g_part[NCHUNK * 16 * HIDn];
__device__ float g_y1[16 * HIDn];

// ------------------------- helpers -------------------------
__device__ __forceinline__ void edge_sd(int e, const int* __restrict__ EI, int& src, int& dst) {
    if (e < EBASE) {
        int b   = e / TWOE;
        int rem = e - b * TWOE;
        src = EI[b * TWOE + rem] + b * Nn;
        int b2 = b + HALFB;
        dst = EI[b2 * TWOE + rem] + b2 * Nn;
    } else {
        src = dst = e - EBASE;
    }
}

__device__ __forceinline__ float warp_sum(float v) {
    #pragma unroll
    for (int o = 16; o > 0; o >>= 1) v += __shfl_xor_sync(0xffffffffu, v, o);
    return v;
}
__device__ __forceinline__ float leaky(float v) { return v > 0.f ? v : 0.2f * v; }
__device__ __forceinline__ float elu(float v)   { return v > 0.f ? v : (__expf(v) - 1.0f); }

__device__ __forceinline__ float2 ffma2(float2 a, float2 b, float2 c) {
    unsigned long long A = *reinterpret_cast<unsigned long long*>(&a);
    unsigned long long B = *reinterpret_cast<unsigned long long*>(&b);
    unsigned long long C = *reinterpret_cast<unsigned long long*>(&c);
    unsigned long long D;
    asm("fma.rn.f32x2 %0, %1, %2, %3;" : "=l"(D) : "l"(A), "l"(B), "l"(C));
    return *reinterpret_cast<float2*>(&D);
}

// ================= build: node features + projections + bucket scatter =================
__global__ void build_kernel(const float* __restrict__ actions,
                             const float* __restrict__ nodef,
                             const float* __restrict__ W1,
                             const float* __restrict__ as1,
                             const float* __restrict__ ad1,
                             const int* __restrict__ EI) {
    int blk = blockIdx.x;
    if (blk < 63) {
        int n = blk * 256 + threadIdx.x;
        if (n >= NT) return;
        float ax = actions[n * 2 + 0];
        float ay = actions[n * 2 + 1];
        float nf = nodef[n];
        g_xf[n] = make_float4(ax, ay, nf, 0.f);
    } else if (blk == 63) {
        int t = threadIdx.x;
        if (t < 48) {
            int which = t / 24;
            int r = t % 24;
            int k = r / 8, h = r % 8;
            const float* att = which ? ad1 : as1;
            float s = 0.f;
            for (int c = 0; c < 128; c++)
                s += W1[k * F1 + h * 128 + c] * att[h * 128 + c];
            (which ? g_pdst : g_psrc)[k * 8 + h] = s;
        }
    } else {
        int idx = (blk - 64) * 256 + threadIdx.x;
        #pragma unroll
        for (int q = 0; q < 4; q++) {
            int e = idx * 4 + q;
            if (e < ETOT) {
                int src, dst;
                edge_sd(e, EI, src, dst);
                if (dst >= NLOW) {
                    int pos = atomicAdd(&g_cursor[dst], 1);
                    g_bucket[dst * BCAP + pos] = src;
                }
            }
        }
    }
}

// ================= conv1: thread per (dst, head); low half = identity =================
__global__ __launch_bounds__(256) void conv1_kernel() {
    int gidx = blockIdx.x * 256 + threadIdx.x;
    if (gidx < 8000) {
        int d = gidx;
        float4 x = g_xf[d];
        float4 v0 = make_float4(x.x, x.y, x.z, x.x);
        float4 v1 = make_float4(x.y, x.z, x.x, x.y);
        float4 v2 = make_float4(x.z, x.x, x.y, x.z);
        float4* sp = (float4*)(g_s + d * 24);
        sp[0] = v0; sp[1] = v1; sp[2] = v2;
        sp[3] = v0; sp[4] = v1; sp[5] = v2;
    } else if (gidx < 8000 + 64000) {
        int i2 = gidx - 8000;
        int d = NLOW + (i2 >> 3), h = i2 & 7;
        float4 xd = g_xf[d];
        float p0 = g_psrc[h], p1 = g_psrc[8 + h], p2 = g_psrc[16 + h];
        float q0 = g_pdst[h], q1 = g_pdst[8 + h], q2 = g_pdst[16 + h];
        float adv = fmaf(xd.x, q0, fmaf(xd.y, q1, xd.z * q2));
        int deg = g_cursor[d];
        const int* bkt = g_bucket + d * BCAP;
        float se = 0.f, sx = 0.f, sy = 0.f, sz = 0.f;
        for (int e = 0; e < deg; e++) {
            int s = bkt[e];
            float4 x = g_xf[s];
            float a = fmaf(x.x, p0, fmaf(x.y, p1, x.z * p2)) + adv;
            float ea = __expf(leaky(a));
            se += ea;
            sx = fmaf(ea, x.x, sx);
            sy = fmaf(ea, x.y, sy);
            sz = fmaf(ea, x.z, sz);
        }
        float inv = 1.0f / se;
        float* sp = g_s + d * 24 + h * 3;
        sp[0] = sx * inv; sp[1] = sy * inv; sp[2] = sz * inv;
    }
}

// ================= fgemm: 8x8 register-tiled  h2 = elu(s@W1+b1) @ W2  + attn2 =================
#define GR 128    /* rows per block */
#define KC 16     /* k-chunk */

__global__ __launch_bounds__(128) void fgemm_kernel(
    const float* __restrict__ W1, const float* __restrict__ b1,
    const float* __restrict__ W2, const float* __restrict__ as2,
    const float* __restrict__ ad2)
{
    __shared__ __align__(16) float4 w1t[F1];           // 16 KB {W1r0,W1r1,W1r2,b1}
    __shared__ float  sS[GR * 24];                     // 12 KB
    __shared__ __align__(16) float2 Adup[2][KC][GR];   // 32 KB
    __shared__ __align__(16) float  Bs[2][KC][EMBn];   //  8 KB

    int tid = threadIdx.x;
    int row0 = blockIdx.x * GR;
    int tr = tid >> 3;            // 0..15 row-group (rows tr*8..+7)
    int tc = tid & 7;             // 0..7  col-group (cols tc*8..+7)

    for (int k = tid; k < F1; k += 128)
        w1t[k] = make_float4(W1[k], W1[F1 + k], W1[2 * F1 + k], b1[k]);
    for (int i = tid; i < GR * 24; i += 128)
        sS[i] = g_s[row0 * 24 + i];
    __syncthreads();

    // s for this thread's build row (row = tid)
    float2 acc[8][4];
    #pragma unroll
    for (int i = 0; i < 8; i++)
        #pragma unroll
        for (int j = 0; j < 4; j++) acc[i][j] = make_float2(0.f, 0.f);

    #define FG_BUILD(ch, buf)                                                     \
    {                                                                             \
        int k0_ = (ch) * KC;                                                      \
        int h_ = k0_ >> 7;                                                        \
        float s0 = sS[tid * 24 + h_ * 3 + 0];                                     \
        float s1 = sS[tid * 24 + h_ * 3 + 1];                                     \
        float s2 = sS[tid * 24 + h_ * 3 + 2];                                     \
        _Pragma("unroll")                                                         \
        for (int kk = 0; kk < KC; kk++) {                                         \
            float4 w = w1t[k0_ + kk];                                             \
            float z = fmaf(s0, w.x, fmaf(s1, w.y, fmaf(s2, w.z, w.w)));           \
            z = elu(z);                                                           \
            Adup[buf][kk][tid] = make_float2(z, z);                               \
        }                                                                         \
        _Pragma("unroll")                                                         \
        for (int t = 0; t < 2; t++) {                                             \
            int q = tid * 2 + t;                                                  \
            int kk = q >> 4, c4 = (q & 15) * 4;                                   \
            *(float4*)&Bs[buf][kk][c4] = *(const float4*)&W2[(k0_ + kk) * EMBn + c4]; \
        }                                                                         \
    }

    FG_BUILD(0, 0)
    __syncthreads();

    for (int c = 0; c < F1 / KC; c++) {
        int cur = c & 1;
        if (c + 1 < F1 / KC) FG_BUILD(c + 1, (c + 1) & 1)
        #pragma unroll 4
        for (int kk = 0; kk < KC; kk++) {
            float4 A0 = *(const float4*)&Adup[cur][kk][tr * 8 + 0];   // rows 0,1 dup
            float4 A1 = *(const float4*)&Adup[cur][kk][tr * 8 + 2];   // rows 2,3
            float4 A2 = *(const float4*)&Adup[cur][kk][tr * 8 + 4];   // rows 4,5
            float4 A3 = *(const float4*)&Adup[cur][kk][tr * 8 + 6];   // rows 6,7
            float4 B0 = *(const float4*)&Bs[cur][kk][tc * 8];         // cols 0..3
            float4 B1 = *(const float4*)&Bs[cur][kk][tc * 8 + 4];     // cols 4..7
            float2 b0 = make_float2(B0.x, B0.y);
            float2 b1v = make_float2(B0.z, B0.w);
            float2 b2v = make_float2(B1.x, B1.y);
            float2 b3 = make_float2(B1.z, B1.w);
            float2 a[8];
            a[0] = make_float2(A0.x, A0.y); a[1] = make_float2(A0.z, A0.w);
            a[2] = make_float2(A1.x, A1.y); a[3] = make_float2(A1.z, A1.w);
            a[4] = make_float2(A2.x, A2.y); a[5] = make_float2(A2.z, A2.w);
            a[6] = make_float2(A3.x, A3.y); a[7] = make_float2(A3.z, A3.w);
            #pragma unroll
            for (int i = 0; i < 8; i++) {
                acc[i][0] = ffma2(a[i], b0, acc[i][0]);
                acc[i][1] = ffma2(a[i], b1v, acc[i][1]);
                acc[i][2] = ffma2(a[i], b2v, acc[i][2]);
                acc[i][3] = ffma2(a[i], b3, acc[i][3]);
            }
        }
        __syncthreads();
    }

    // store h2: 8 rows x 8 cols per thread
    #pragma unroll
    for (int i = 0; i < 8; i++) {
        int r = row0 + tr * 8 + i;
        float4 o0 = make_float4(acc[i][0].x, acc[i][0].y, acc[i][1].x, acc[i][1].y);
        float4 o1 = make_float4(acc[i][2].x, acc[i][2].y, acc[i][3].x, acc[i][3].y);
        *(float4*)&g_h2[r * EMBn + tc * 8]     = o0;
        *(float4*)&g_h2[r * EMBn + tc * 8 + 4] = o1;
    }

    // attn2 epilogue: per-thread partials over its 8 cols, reduce over tc (lanes &7)
    float2 asp[4], adp[4];
    #pragma unroll
    for (int jp = 0; jp < 4; jp++) {
        asp[jp] = make_float2(as2[tc * 8 + 2 * jp], as2[tc * 8 + 2 * jp + 1]);
        adp[jp] = make_float2(ad2[tc * 8 + 2 * jp], ad2[tc * 8 + 2 * jp + 1]);
    }
    #pragma unroll
    for (int i = 0; i < 8; i++) {
        float ss = 0.f, sd = 0.f;
        #pragma unroll
        for (int jp = 0; jp < 4; jp++) {
            ss += acc[i][jp].x * asp[jp].x + acc[i][jp].y * asp[jp].y;
            sd += acc[i][jp].x * adp[jp].x + acc[i][jp].y * adp[jp].y;
        }
        #pragma unroll
        for (int o = 1; o < 8; o <<= 1) {
            ss += __shfl_xor_sync(0xffffffffu, ss, o);
            sd += __shfl_xor_sync(0xffffffffu, sd, o);
        }
        if (tc == 0) {
            g_a2s[row0 + tr * 8 + i] = ss;
            g_a2d[row0 + tr * 8 + i] = sd;
        }
    }
}

// ================= conv2: warp per heavy dst; low half elementwise =================
__global__ __launch_bounds__(256) void conv2_kernel(const float* __restrict__ b2) {
    __shared__ float wbuf[8][BCAP];
    __shared__ int   ibuf[8][BCAP];
    int tid = threadIdx.x;
    int gidx = blockIdx.x * 256 + tid;
    int lane = tid & 31;
    int w = tid >> 5;
    int wg = gidx >> 5;                         // 8000 warps
    {
        int d = NLOW + wg;
        int deg = g_cursor[d];
        const int* bkt = g_bucket + d * BCAP;
        float adv = g_a2d[d];
        float se = 0.f;
        for (int e = lane; e < deg; e += 32) {
            int src = bkt[e];
            float ea = __expf(leaky(g_a2s[src] + adv));
            wbuf[w][e] = ea;
            ibuf[w][e] = src;
            se += ea;
        }
        __syncwarp();
        float2 acc = make_float2(0.f, 0.f);
        #pragma unroll 4
        for (int e = 0; e < deg; e++) {
            float ea = wbuf[w][e];
            int src = ibuf[w][e];
            float2 v = ((const float2*)(g_h2 + src * 64))[lane];
            acc.x = fmaf(ea, v.x, acc.x);
            acc.y = fmaf(ea, v.y, acc.y);
        }
        __syncwarp();
        se = warp_sum(se);
        float inv = 1.0f / se;
        float2 bb = ((const float2*)b2)[lane];
        int b = d / Nn, n = d - b * Nn;
        int c = lane * 2;
        g_x2t[(n * 64 + c) * 16 + b]     = elu(acc.x * inv + bb.x);
        g_x2t[(n * 64 + c + 1) * 16 + b] = elu(acc.y * inv + bb.y);
    }
    {   // low half: one (d, lane) element pair per thread: 8000*32 = 256000 = grid exactly
        int d = gidx >> 5, ln = gidx & 31;
        float2 v = ((const float2*)(g_h2 + d * 64))[ln];
        float2 bb = ((const float2*)b2)[ln];
        int b = d / Nn, n = d - b * Nn;
        int c = ln * 2;
        g_x2t[(n * 64 + c) * 16 + b]     = elu(v.x + bb.x);
        g_x2t[(n * 64 + c + 1) * 16 + b] = elu(v.y + bb.y);
    }
}

// ================= mlp1 split-K stage 1 (+ cursor reset) =================
__global__ __launch_bounds__(128) void mlp1_kernel(const float* __restrict__ mw1) {
    __shared__ __align__(16) float sx[CK * 16];
    int cblk = blockIdx.x;
    int tid = threadIdx.x;
    int zid = cblk * 128 + tid;
    if (zid < NT) g_cursor[zid] = 0;
    int k0 = cblk * CK;
    const float4* gx4 = (const float4*)(g_x2t + k0 * 16);
    float4* sx4 = (float4*)sx;
    #pragma unroll
    for (int i = 0; i < 5; i++)
        sx4[tid + i * 128] = gx4[tid + i * 128];
    __syncthreads();
    int j = tid;
    float2 acc[8];
    #pragma unroll
    for (int p = 0; p < 8; p++) acc[p] = make_float2(0.f, 0.f);
    #pragma unroll 2
    for (int k = 0; k < CK; k++) {
        float wv = mw1[(k0 + k) * HIDn + j];
        float2 w2v = make_float2(wv, wv);
        float4 x0 = sx4[k * 4 + 0];
        float4 x1 = sx4[k * 4 + 1];
        float4 x2 = sx4[k * 4 + 2];
        float4 x3 = sx4[k * 4 + 3];
        acc[0] = ffma2(make_float2(x0.x, x0.y), w2v, acc[0]);
        acc[1] = ffma2(make_float2(x0.z, x0.w), w2v, acc[1]);
        acc[2] = ffma2(make_float2(x1.x, x1.y), w2v, acc[2]);
        acc[3] = ffma2(make_float2(x1.z, x1.w), w2v, acc[3]);
        acc[4] = ffma2(make_float2(x2.x, x2.y), w2v, acc[4]);
        acc[5] = ffma2(make_float2(x2.z, x2.w), w2v, acc[5]);
        acc[6] = ffma2(make_float2(x3.x, x3.y), w2v, acc[6]);
        acc[7] = ffma2(make_float2(x3.z, x3.w), w2v, acc[7]);
    }
    #pragma unroll
    for (int p = 0; p < 8; p++) {
        g_part[(cblk * 16 + 2 * p) * HIDn + j]     = acc[p].x;
        g_part[(cblk * 16 + 2 * p + 1) * HIDn + j] = acc[p].y;
    }
}

__global__ void reduce_kernel(const float* __restrict__ mb1) {
    int idx = blockIdx.x * 128 + threadIdx.x;
    if (idx >= 16 * HIDn) return;
    int b = idx >> 7, j = idx & 127;
    float s = 0.f;
    #pragma unroll 4
    for (int c = 0; c < NCHUNK; c++)
        s += g_part[(c * 16 + b) * HIDn + j];
    s += mb1[j];
    g_y1[b * HIDn + j] = fmaxf(s, 0.f);
}

// ================= tail: mlp2 (redundant per block) + output head =================
__global__ __launch_bounds__(256) void tail_kernel(
    const float* __restrict__ mw2, const float* __restrict__ mb2,
    const float* __restrict__ ow,  const float* __restrict__ ob,
    float* __restrict__ out)
{
    __shared__ float y1s[16 * HIDn];
    __shared__ float y2s[16 * HIDn];
    int tid = threadIdx.x;
    int bid = blockIdx.x;
    for (int i = tid; i < 16 * HIDn; i += 256) y1s[i] = g_y1[i];
    __syncthreads();
    if (tid < 128) {
        int j = tid;
        float acc[16];
        #pragma unroll
        for (int b = 0; b < 16; b++) acc[b] = 0.f;
        #pragma unroll 4
        for (int k = 0; k < HIDn; k++) {
            float wv = mw2[k * HIDn + j];
            #pragma unroll
            for (int b = 0; b < 16; b++)
                acc[b] = fmaf(y1s[b * HIDn + k], wv, acc[b]);
        }
        #pragma unroll
        for (int b = 0; b < 16; b++)
            y2s[b * HIDn + j] = fmaxf(acc[b] + mb2[j], 0.f);
    }
    __syncthreads();
    int j = bid * 128 + (tid & 127);
    int bh = tid >> 7;
    if (j < Nn) {
        float acc[8];
        #pragma unroll
        for (int b = 0; b < 8; b++) acc[b] = 0.f;
        const float* y = y2s + bh * 8 * HIDn;
        #pragma unroll 4
        for (int k = 0; k < HIDn; k++) {
            float wv = ow[k * Nn + j];
            #pragma unroll
            for (int b = 0; b < 8; b++)
                acc[b] = fmaf(y[b * HIDn + k], wv, acc[b]);
        }
        float obj = ob[j];
        #pragma unroll
        for (int b = 0; b < 8; b++) {
            float v = acc[b] + obj;
            out[(bh * 8 + b) * Nn + j] = 1.0f / (1.0f + __expf(-v));
        }
    }
}

// ------------------------- launch -------------------------
extern "C" void kernel_launch(void* const* d_in, const int* in_sizes, int n_in,
                              void* d_out, int out_size) {
    const float* actions = (const float*)d_in[0];
    const float* nodef   = (const float*)d_in[1];
    const int*   ei      = (const int*)d_in[2];
    const float* W1  = (const float*)d_in[3];
    const float* as1 = (const float*)d_in[4];
    const float* ad1 = (const float*)d_in[5];
    const float* b1  = (const float*)d_in[6];
    const float* W2  = (const float*)d_in[7];
    const float* as2 = (const float*)d_in[8];
    const float* ad2 = (const float*)d_in[9];
    const float* b2  = (const float*)d_in[10];
    const float* mw1 = (const float*)d_in[11];
    const float* mb1 = (const float*)d_in[12];
    const float* mw2 = (const float*)d_in[13];
    const float* mb2 = (const float*)d_in[14];
    const float* ow  = (const float*)d_in[15];
    const float* ob  = (const float*)d_in[16];
    float* out = (float*)d_out;

    build_kernel<<<330, 256>>>(actions, nodef, W1, as1, ad1, ei);
    conv1_kernel<<<282, 256>>>();
    fgemm_kernel<<<125, 128>>>(W1, b1, W2, as2, ad2);
    conv2_kernel<<<1000, 256>>>(b2);
    mlp1_kernel<<<NCHUNK, 128>>>(mw1);
    reduce_kernel<<<16, 128>>>(mb1);
    tail_kernel<<<8, 256>>>(mw2, mb2, ow, ob, out);
}

// round 12
// speedup vs baseline: 1.3413x; 1.2305x over previous
#include <cuda_runtime.h>
#include <math.h>

#define Bn 16
#define Nn 1000
#define En 16000
#define NT 16000
#define EBASE 256000
#define ETOT 272000
#define TWOE 32000
#define HALFB 8
#define NLOW 8000         /* dsts 0..7999 have only their self loop (structural) */

#define H1n 8
#define F1 1024
#define EMBn 64
#define HIDn 128
#define BCAP 96

#define NCHUNK 400
#define CK 160

// ------------------------- scratch -------------------------
__device__ __align__(16) float4 g_xf[NT];
__device__ float g_psrc[24];
__device__ float g_pdst[24];
__device__ int   g_cursor[NT];                 // zero at load; re-zeroed in mlp1
__device__ int   g_bucket[NT * BCAP];
__device__ __align__(16) float g_s[NT * 24];
__device__ __align__(16) float g_h2[NT * EMBn];
__device__ float g_a2s[NT];
__device__ float g_a2d[NT];
__device__ __align__(16) float g_x2t[64000 * 16];
__device__ float g_part[NCHUNK * 16 * HIDn];
__device__ float g_y1[16 * HIDn];

// ------------------------- helpers -------------------------
__device__ __forceinline__ void edge_sd(int e, const int* __restrict__ EI, int& src, int& dst) {
    if (e < EBASE) {
        int b   = e / TWOE;
        int rem = e - b * TWOE;
        src = EI[b * TWOE + rem] + b * Nn;
        int b2 = b + HALFB;
        dst = EI[b2 * TWOE + rem] + b2 * Nn;
    } else {
        src = dst = e - EBASE;
    }
}

__device__ __forceinline__ float warp_sum(float v) {
    #pragma unroll
    for (int o = 16; o > 0; o >>= 1) v += __shfl_xor_sync(0xffffffffu, v, o);
    return v;
}
__device__ __forceinline__ float leaky(float v) { return v > 0.f ? v : 0.2f * v; }
__device__ __forceinline__ float elu(float v)   { return v > 0.f ? v : (__expf(v) - 1.0f); }

__device__ __forceinline__ float2 ffma2(float2 a, float2 b, float2 c) {
    unsigned long long A = *reinterpret_cast<unsigned long long*>(&a);
    unsigned long long B = *reinterpret_cast<unsigned long long*>(&b);
    unsigned long long C = *reinterpret_cast<unsigned long long*>(&c);
    unsigned long long D;
    asm("fma.rn.f32x2 %0, %1, %2, %3;" : "=l"(D) : "l"(A), "l"(B), "l"(C));
    return *reinterpret_cast<float2*>(&D);
}

// ================= build: node features + projections + bucket scatter =================
__global__ void build_kernel(const float* __restrict__ actions,
                             const float* __restrict__ nodef,
                             const float* __restrict__ W1,
                             const float* __restrict__ as1,
                             const float* __restrict__ ad1,
                             const int* __restrict__ EI) {
    int blk = blockIdx.x;
    if (blk < 63) {
        int n = blk * 256 + threadIdx.x;
        if (n >= NT) return;
        float ax = actions[n * 2 + 0];
        float ay = actions[n * 2 + 1];
        float nf = nodef[n];
        g_xf[n] = make_float4(ax, ay, nf, 0.f);
    } else if (blk == 63) {
        int t = threadIdx.x;
        if (t < 48) {
            int which = t / 24;
            int r = t % 24;
            int k = r / 8, h = r % 8;
            const float* att = which ? ad1 : as1;
            float s = 0.f;
            for (int c = 0; c < 128; c++)
                s += W1[k * F1 + h * 128 + c] * att[h * 128 + c];
            (which ? g_pdst : g_psrc)[k * 8 + h] = s;
        }
    } else {
        int idx = (blk - 64) * 256 + threadIdx.x;
        #pragma unroll
        for (int q = 0; q < 4; q++) {
            int e = idx * 4 + q;
            if (e < ETOT) {
                int src, dst;
                edge_sd(e, EI, src, dst);
                if (dst >= NLOW) {
                    int pos = atomicAdd(&g_cursor[dst], 1);
                    g_bucket[dst * BCAP + pos] = src;
                }
            }
        }
    }
}

// ================= conv1: thread per (dst, head); low half = identity =================
__global__ __launch_bounds__(256) void conv1_kernel() {
    int gidx = blockIdx.x * 256 + threadIdx.x;
    if (gidx < 8000) {
        int d = gidx;
        float4 x = g_xf[d];
        float4 v0 = make_float4(x.x, x.y, x.z, x.x);
        float4 v1 = make_float4(x.y, x.z, x.x, x.y);
        float4 v2 = make_float4(x.z, x.x, x.y, x.z);
        float4* sp = (float4*)(g_s + d * 24);
        sp[0] = v0; sp[1] = v1; sp[2] = v2;
        sp[3] = v0; sp[4] = v1; sp[5] = v2;
    } else if (gidx < 8000 + 64000) {
        int i2 = gidx - 8000;
        int d = NLOW + (i2 >> 3), h = i2 & 7;
        float4 xd = g_xf[d];
        float p0 = g_psrc[h], p1 = g_psrc[8 + h], p2 = g_psrc[16 + h];
        float q0 = g_pdst[h], q1 = g_pdst[8 + h], q2 = g_pdst[16 + h];
        float adv = fmaf(xd.x, q0, fmaf(xd.y, q1, xd.z * q2));
        int deg = g_cursor[d];
        const int* bkt = g_bucket + d * BCAP;
        float se = 0.f, sx = 0.f, sy = 0.f, sz = 0.f;
        for (int e = 0; e < deg; e++) {
            int s = bkt[e];
            float4 x = g_xf[s];
            float a = fmaf(x.x, p0, fmaf(x.y, p1, x.z * p2)) + adv;
            float ea = __expf(leaky(a));
            se += ea;
            sx = fmaf(ea, x.x, sx);
            sy = fmaf(ea, x.y, sy);
            sz = fmaf(ea, x.z, sz);
        }
        float inv = 1.0f / se;
        float* sp = g_s + d * 24 + h * 3;
        sp[0] = sx * inv; sp[1] = sy * inv; sp[2] = sz * inv;
    }
}

// ================= fgemm: broadcast-GEMM, full activity =================
// 125 blocks x 256 threads. Block covers 128 rows (16000 = 125*128 exactly).
// slot = tid&127 -> row; half = tid>>7 -> 32-col half (warp-uniform).
// Per k: 1 broadcast w1t float4 + 8 broadcast W2 float4 + 16 FFMA2.
__global__ __launch_bounds__(256) void fgemm_kernel(
    const float* __restrict__ W1, const float* __restrict__ b1,
    const float* __restrict__ W2, const float* __restrict__ as2,
    const float* __restrict__ ad2)
{
    __shared__ __align__(16) float4 w1t[F1];       // 16 KB {W1r0,W1r1,W1r2,b1}
    __shared__ __align__(16) float  w2c[128][EMBn]; // 32 KB chunk (reused as scratch)
    __shared__ float sS[128 * 24];                  // 12 KB
    __shared__ float satt[128];                     // as2 | ad2

    int tid = threadIdx.x;
    int bid = blockIdx.x;
    int half = tid >> 7;            // warp-uniform
    int slot = tid & 127;
    int row = bid * 128 + slot;

    for (int k = tid; k < F1; k += 256)
        w1t[k] = make_float4(W1[k], W1[F1 + k], W1[2 * F1 + k], b1[k]);
    for (int i = tid; i < 128 * 24; i += 256)
        sS[i] = g_s[bid * 128 * 24 + i];
    if (tid < 128) satt[tid] = (tid < 64) ? as2[tid] : ad2[tid - 64];

    float2 acc[16];
    #pragma unroll
    for (int j = 0; j < 16; j++) acc[j] = make_float2(0.f, 0.f);

    for (int ch = 0; ch < 8; ch++) {
        __syncthreads();
        {   // stage W2 chunk: 128 k-rows x 64 cols = 2048 float4
            const float4* w2g = (const float4*)(W2 + ch * 128 * EMBn);
            float4* w2s = (float4*)w2c;
            #pragma unroll
            for (int i = 0; i < 8; i++)
                w2s[tid + i * 256] = w2g[tid + i * 256];
        }
        __syncthreads();
        float s0 = sS[slot * 24 + ch * 3 + 0];
        float s1 = sS[slot * 24 + ch * 3 + 1];
        float s2 = sS[slot * 24 + ch * 3 + 2];
        #pragma unroll 4
        for (int k = 0; k < 128; k++) {
            float4 w = w1t[ch * 128 + k];                          // broadcast
            float x1 = fmaf(s0, w.x, fmaf(s1, w.y, fmaf(s2, w.z, w.w)));
            x1 = elu(x1);
            float2 xx = make_float2(x1, x1);
            const float4* brow = (const float4*)&w2c[k][half * 32]; // broadcast
            #pragma unroll
            for (int j = 0; j < 8; j++) {
                float4 b = brow[j];
                acc[j * 2]     = ffma2(xx, make_float2(b.x, b.y), acc[j * 2]);
                acc[j * 2 + 1] = ffma2(xx, make_float2(b.z, b.w), acc[j * 2 + 1]);
            }
        }
    }
    // store h2 (32 cols per thread)
    {
        float4* dst = (float4*)(g_h2 + row * 64 + half * 32);
        const float4* a4 = (const float4*)acc;
        #pragma unroll
        for (int j = 0; j < 8; j++) dst[j] = a4[j];
    }
    // attn2 epilogue: per-thread partials, combine halves via smem
    float ss = 0.f, sd = 0.f;
    {
        const float* av = (const float*)acc;
        #pragma unroll
        for (int j = 0; j < 32; j++) {
            float v = av[j];
            ss = fmaf(v, satt[half * 32 + j], ss);
            sd = fmaf(v, satt[64 + half * 32 + j], sd);
        }
    }
    __syncthreads();
    float* red = w2c[0];
    red[tid] = ss; red[256 + tid] = sd;
    __syncthreads();
    if (half == 0) {
        g_a2s[row] = red[tid] + red[tid + 128];
        g_a2d[row] = red[256 + tid] + red[256 + tid + 128];
    }
}

// ================= conv2: warp per heavy dst; low half elementwise =================
__global__ __launch_bounds__(256) void conv2_kernel(const float* __restrict__ b2) {
    __shared__ float wbuf[8][BCAP];
    __shared__ int   ibuf[8][BCAP];
    int tid = threadIdx.x;
    int gidx = blockIdx.x * 256 + tid;
    int lane = tid & 31;
    int w = tid >> 5;
    int wg = gidx >> 5;                         // 8000 warps
    {
        int d = NLOW + wg;
        int deg = g_cursor[d];
        const int* bkt = g_bucket + d * BCAP;
        float adv = g_a2d[d];
        float se = 0.f;
        for (int e = lane; e < deg; e += 32) {
            int src = bkt[e];
            float ea = __expf(leaky(g_a2s[src] + adv));
            wbuf[w][e] = ea;
            ibuf[w][e] = src;
            se += ea;
        }
        __syncwarp();
        float2 acc = make_float2(0.f, 0.f);
        #pragma unroll 4
        for (int e = 0; e < deg; e++) {
            float ea = wbuf[w][e];
            int src = ibuf[w][e];
            float2 v = ((const float2*)(g_h2 + src * 64))[lane];
            acc.x = fmaf(ea, v.x, acc.x);
            acc.y = fmaf(ea, v.y, acc.y);
        }
        __syncwarp();
        se = warp_sum(se);
        float inv = 1.0f / se;
        float2 bb = ((const float2*)b2)[lane];
        int b = d / Nn, n = d - b * Nn;
        int c = lane * 2;
        g_x2t[(n * 64 + c) * 16 + b]     = elu(acc.x * inv + bb.x);
        g_x2t[(n * 64 + c + 1) * 16 + b] = elu(acc.y * inv + bb.y);
    }
    {   // low half: 8000*32 threads exactly
        int d = gidx >> 5, ln = gidx & 31;
        float2 v = ((const float2*)(g_h2 + d * 64))[ln];
        float2 bb = ((const float2*)b2)[ln];
        int b = d / Nn, n = d - b * Nn;
        int c = ln * 2;
        g_x2t[(n * 64 + c) * 16 + b]     = elu(v.x + bb.x);
        g_x2t[(n * 64 + c + 1) * 16 + b] = elu(v.y + bb.y);
    }
}

// ================= mlp1 split-K stage 1 (+ cursor reset) =================
__global__ __launch_bounds__(128) void mlp1_kernel(const float* __restrict__ mw1) {
    __shared__ __align__(16) float sx[CK * 16];
    int cblk = blockIdx.x;
    int tid = threadIdx.x;
    int zid = cblk * 128 + tid;
    if (zid < NT) g_cursor[zid] = 0;
    int k0 = cblk * CK;
    const float4* gx4 = (const float4*)(g_x2t + k0 * 16);
    float4* sx4 = (float4*)sx;
    #pragma unroll
    for (int i = 0; i < 5; i++)
        sx4[tid + i * 128] = gx4[tid + i * 128];
    __syncthreads();
    int j = tid;
    float2 acc[8];
    #pragma unroll
    for (int p = 0; p < 8; p++) acc[p] = make_float2(0.f, 0.f);
    #pragma unroll 2
    for (int k = 0; k < CK; k++) {
        float wv = mw1[(k0 + k) * HIDn + j];
        float2 w2v = make_float2(wv, wv);
        float4 x0 = sx4[k * 4 + 0];
        float4 x1 = sx4[k * 4 + 1];
        float4 x2 = sx4[k * 4 + 2];
        float4 x3 = sx4[k * 4 + 3];
        acc[0] = ffma2(make_float2(x0.x, x0.y), w2v, acc[0]);
        acc[1] = ffma2(make_float2(x0.z, x0.w), w2v, acc[1]);
        acc[2] = ffma2(make_float2(x1.x, x1.y), w2v, acc[2]);
        acc[3] = ffma2(make_float2(x1.z, x1.w), w2v, acc[3]);
        acc[4] = ffma2(make_float2(x2.x, x2.y), w2v, acc[4]);
        acc[5] = ffma2(make_float2(x2.z, x2.w), w2v, acc[5]);
        acc[6] = ffma2(make_float2(x3.x, x3.y), w2v, acc[6]);
        acc[7] = ffma2(make_float2(x3.z, x3.w), w2v, acc[7]);
    }
    #pragma unroll
    for (int p = 0; p < 8; p++) {
        g_part[(cblk * 16 + 2 * p) * HIDn + j]     = acc[p].x;
        g_part[(cblk * 16 + 2 * p + 1) * HIDn + j] = acc[p].y;
    }
}

__global__ void reduce_kernel(const float* __restrict__ mb1) {
    int idx = blockIdx.x * 128 + threadIdx.x;
    if (idx >= 16 * HIDn) return;
    int b = idx >> 7, j = idx & 127;
    float s = 0.f;
    #pragma unroll 4
    for (int c = 0; c < NCHUNK; c++)
        s += g_part[(c * 16 + b) * HIDn + j];
    s += mb1[j];
    g_y1[b * HIDn + j] = fmaxf(s, 0.f);
}

// ================= tail: mlp2 (redundant per block) + output head =================
__global__ __launch_bounds__(256) void tail_kernel(
    const float* __restrict__ mw2, const float* __restrict__ mb2,
    const float* __restrict__ ow,  const float* __restrict__ ob,
    float* __restrict__ out)
{
    __shared__ float y1s[16 * HIDn];
    __shared__ float y2s[16 * HIDn];
    int tid = threadIdx.x;
    int bid = blockIdx.x;
    for (int i = tid; i < 16 * HIDn; i += 256) y1s[i] = g_y1[i];
    __syncthreads();
    if (tid < 128) {
        int j = tid;
        float acc[16];
        #pragma unroll
        for (int b = 0; b < 16; b++) acc[b] = 0.f;
        #pragma unroll 4
        for (int k = 0; k < HIDn; k++) {
            float wv = mw2[k * HIDn + j];
            #pragma unroll
            for (int b = 0; b < 16; b++)
                acc[b] = fmaf(y1s[b * HIDn + k], wv, acc[b]);
        }
        #pragma unroll
        for (int b = 0; b < 16; b++)
            y2s[b * HIDn + j] = fmaxf(acc[b] + mb2[j], 0.f);
    }
    __syncthreads();
    int j = bid * 128 + (tid & 127);
    int bh = tid >> 7;
    if (j < Nn) {
        float acc[8];
        #pragma unroll
        for (int b = 0; b < 8; b++) acc[b] = 0.f;
        const float* y = y2s + bh * 8 * HIDn;
        #pragma unroll 4
        for (int k = 0; k < HIDn; k++) {
            float wv = ow[k * Nn + j];
            #pragma unroll
            for (int b = 0; b < 8; b++)
                acc[b] = fmaf(y[b * HIDn + k], wv, acc[b]);
        }
        float obj = ob[j];
        #pragma unroll
        for (int b = 0; b < 8; b++) {
            float v = acc[b] + obj;
            out[(bh * 8 + b) * Nn + j] = 1.0f / (1.0f + __expf(-v));
        }
    }
}

// ------------------------- launch -------------------------
extern "C" void kernel_launch(void* const* d_in, const int* in_sizes, int n_in,
                              void* d_out, int out_size) {
    const float* actions = (const float*)d_in[0];
    const float* nodef   = (const float*)d_in[1];
    const int*   ei      = (const int*)d_in[2];
    const float* W1  = (const float*)d_in[3];
    const float* as1 = (const float*)d_in[4];
    const float* ad1 = (const float*)d_in[5];
    const float* b1  = (const float*)d_in[6];
    const float* W2  = (const float*)d_in[7];
    const float* as2 = (const float*)d_in[8];
    const float* ad2 = (const float*)d_in[9];
    const float* b2  = (const float*)d_in[10];
    const float* mw1 = (const float*)d_in[11];
    const float* mb1 = (const float*)d_in[12];
    const float* mw2 = (const float*)d_in[13];
    const float* mb2 = (const float*)d_in[14];
    const float* ow  = (const float*)d_in[15];
    const float* ob  = (const float*)d_in[16];
    float* out = (float*)d_out;

    build_kernel<<<330, 256>>>(actions, nodef, W1, as1, ad1, ei);
    conv1_kernel<<<282, 256>>>();
    fgemm_kernel<<<125, 256>>>(W1, b1, W2, as2, ad2);
    conv2_kernel<<<1000, 256>>>(b2);
    mlp1_kernel<<<NCHUNK, 128>>>(mw1);
    reduce_kernel<<<16, 128>>>(mb1);
    tail_kernel<<<8, 256>>>(mw2, mb2, ow, ob, out);
}